// round 15
// baseline (speedup 1.0000x reference)
#include <cuda_runtime.h>
#include <cstdint>

// RoiAlign FPN: B=2, N=1000, CROP=7x7, C=256, levels 256/128/64/32/16 (NHWC f32).
// 444 blocks x 256 threads (3 CTAs/SM => 24 warps/SM); each block owns 4-5
// contiguous boxes. Phase 1: per-pixel params into smem (corner-00 absolute
// byte address + dx/dy deltas in one uint4). Phase 2: flat pixel loop,
// 4 slots x 64 float4 channel groups, DEPTH-3 software pipeline via manual
// 3-body unroll with static register sets (no rotation MOVs).

#define COMPUTE_AND_REFILL(S00, S01, S10, S11, QB, Q, NEXTQ)                  \
    do {                                                                      \
        const int q_ = (Q);                                                   \
        const float lx_ = QB.x, ly_ = QB.y, okf_ = QB.z;                      \
        float4 val_;                                                          \
        float t_, btm_;                                                       \
        t_ = S00.x + lx_ * (S01.x - S00.x);                                   \
        btm_ = S10.x + lx_ * (S11.x - S10.x);                                 \
        val_.x = (t_ + ly_ * (btm_ - t_)) * okf_;                             \
        t_ = S00.y + lx_ * (S01.y - S00.y);                                   \
        btm_ = S10.y + lx_ * (S11.y - S10.y);                                 \
        val_.y = (t_ + ly_ * (btm_ - t_)) * okf_;                             \
        t_ = S00.z + lx_ * (S01.z - S00.z);                                   \
        btm_ = S10.z + lx_ * (S11.z - S10.z);                                 \
        val_.z = (t_ + ly_ * (btm_ - t_)) * okf_;                             \
        t_ = S00.w + lx_ * (S01.w - S00.w);                                   \
        btm_ = S10.w + lx_ * (S11.w - S10.w);                                 \
        val_.w = (t_ + ly_ * (btm_ - t_)) * okf_;                             \
        if (q_ < total) out4[(long)q_ * 64] = val_;                           \
        /* tail-safe refill index: always a written entry */                  \
        const int nq_ = ((NEXTQ) < total) ? (NEXTQ)                           \
                        : ((q_ < total) ? q_ : 0);                            \
        const uint4 qa_ = s_a[nq_];                                           \
        QB = s_b[nq_];                                                        \
        const char* base_ = (const char*)                                     \
            (((uint64_t)qa_.y << 32) | qa_.x) + coff;                         \
        S00 = __ldg((const float4*)(base_));                                  \
        S01 = __ldg((const float4*)(base_ + qa_.z));                          \
        S10 = __ldg((const float4*)(base_ + qa_.w));                          \
        S11 = __ldg((const float4*)(base_ + qa_.z + qa_.w));                  \
    } while (0)

__global__ __launch_bounds__(256, 3) void roialign_kernel(
    const float* __restrict__ boxes,
    const float* __restrict__ f0, const float* __restrict__ f1,
    const float* __restrict__ f2, const float* __restrict__ f3,
    const float* __restrict__ f4,
    const int*   __restrict__ image_shape,
    float*       __restrict__ out,
    int N, int chunk, int rem)
{
    __shared__ uint4  s_a[343];     // addr00_lo, addr00_hi, dx_bytes, dy_bytes
    __shared__ float4 s_b[343];     // lx, ly, okf, 0

    const int bid = blockIdx.x;
    const int tid = threadIdx.x;

    const int start = bid * chunk + min(bid, rem);
    const int nb    = chunk + (bid < rem ? 1 : 0);   // 4..5 typical, <=7 max
    const int total = nb * 49;

    // ---------------- Phase 1: params for all nb*49 pixels -------------------
    for (int q = tid; q < total; q += 256) {
        const int bl   = q / 49;
        const int pixl = q % 49;
        const int boxg = start + bl;

        // NOTE: reference unpacks boxes[:,0] as "y1" though setup stacked
        // [x1,y1,x2,y2]; features are square so it's a consistent transpose.
        const float a0 = __ldg(boxes + (size_t)boxg * 4 + 0);
        const float a1 = __ldg(boxes + (size_t)boxg * 4 + 1);
        const float a2 = __ldg(boxes + (size_t)boxg * 4 + 2);
        const float a3 = __ldg(boxes + (size_t)boxg * 4 + 3);

        // lvl = clip(round(log2(sqrt(h*w) / (56/sqrt(area)))), 0, 4)
        const float h     = a3 - a1;
        const float w     = a2 - a0;
        const float area  = (float)(image_shape[0] * image_shape[1]);
        const float denom = 56.0f / sqrtf(area);
        int lvl = (int)rintf(log2f(sqrtf(h * w) / denom));  // round-half-even
        lvl = min(max(lvl, 0), 4);

        const int S = 256 >> lvl;
        const float* feat = (lvl == 0) ? f0 : (lvl == 1) ? f1
                          : (lvl == 2) ? f2 : (lvl == 3) ? f3 : f4;

        const float Hf = (float)(S - 1);
        const int gy = pixl / 7;
        const int gx = pixl % 7;

        // Exact reference op order: ys = y1*Hf + gy*((y2-y1)*Hf/6)
        const float ys = a0 * Hf + (float)gy * (((a2 - a0) * Hf) / 6.0f);
        const float xs = a1 * Hf + (float)gx * (((a3 - a1) * Hf) / 6.0f);

        const float y0f = floorf(ys);
        const float x0f = floorf(xs);
        const float ly  = ys - y0f;
        const float lx  = xs - x0f;

        const int y0 = (int)fminf(fmaxf(y0f,        0.0f), Hf);
        const int y1 = (int)fminf(fmaxf(y0f + 1.0f, 0.0f), Hf);
        const int x0 = (int)fminf(fmaxf(x0f,        0.0f), Hf);
        const int x1 = (int)fminf(fmaxf(x0f + 1.0f, 0.0f), Hf);

        const float okf = ((ys >= 0.0f) & (ys <= Hf) &
                           (xs >= 0.0f) & (xs <= Hf)) ? 1.0f : 0.0f;

        const int bS = (boxg / N) * S;
        // absolute byte address of corner (y0,x0); row stride = S*1024 bytes,
        // col stride = 1024 bytes (C=256 floats)
        const uint64_t addr00 = (uint64_t)feat
                              + ((uint64_t)(bS + y0) * S + x0) * 1024u;
        const uint32_t dx = (uint32_t)(x1 - x0) * 1024u;          // 0 or 1024
        const uint32_t dy = (uint32_t)(y1 - y0) * (uint32_t)S * 1024u;

        s_a[q] = make_uint4((uint32_t)addr00, (uint32_t)(addr00 >> 32), dx, dy);
        s_b[q] = make_float4(lx, ly, okf, 0.0f);
    }
    __syncthreads();

    // ---------------- Phase 2: depth-3, zero-rotation pipeline ---------------
    const int psub = tid >> 6;            // pixel slot 0..3
    const int c    = tid & 63;            // float4 channel group 0..63
    const uint32_t coff = (uint32_t)c * 16u;
    float4* __restrict__ out4 = (float4*)out + (long)start * 49 * 64 + c;

    // Prologue: fill S0 (p), S1 (p+4), S2 (p+8); total>=196 so all valid.
    const int p0 = psub;
    uint4 qa = s_a[p0];
    float4 qbA = s_b[p0];
    const char* baseA = (const char*)(((uint64_t)qa.y << 32) | qa.x) + coff;
    float4 A00 = __ldg((const float4*)(baseA));
    float4 A01 = __ldg((const float4*)(baseA + qa.z));
    float4 A10 = __ldg((const float4*)(baseA + qa.w));
    float4 A11 = __ldg((const float4*)(baseA + qa.z + qa.w));

    qa = s_a[p0 + 4];
    float4 qbB = s_b[p0 + 4];
    const char* baseB = (const char*)(((uint64_t)qa.y << 32) | qa.x) + coff;
    float4 B00 = __ldg((const float4*)(baseB));
    float4 B01 = __ldg((const float4*)(baseB + qa.z));
    float4 B10 = __ldg((const float4*)(baseB + qa.w));
    float4 B11 = __ldg((const float4*)(baseB + qa.z + qa.w));

    qa = s_a[p0 + 8];
    float4 qbC = s_b[p0 + 8];
    const char* baseC = (const char*)(((uint64_t)qa.y << 32) | qa.x) + coff;
    float4 C00 = __ldg((const float4*)(baseC));
    float4 C01 = __ldg((const float4*)(baseC + qa.z));
    float4 C10 = __ldg((const float4*)(baseC + qa.w));
    float4 C11 = __ldg((const float4*)(baseC + qa.z + qa.w));

    #pragma unroll 1
    for (int p = p0; p < total; p += 12) {
        // body 0: pixel p, refill S0 with p+12 (used 3 bodies later)
        COMPUTE_AND_REFILL(A00, A01, A10, A11, qbA, p,      p + 12);
        // body 1: pixel p+4, refill S1 with p+16
        COMPUTE_AND_REFILL(B00, B01, B10, B11, qbB, p + 4,  p + 16);
        // body 2: pixel p+8, refill S2 with p+20
        COMPUTE_AND_REFILL(C00, C01, C10, C11, qbC, p + 8,  p + 20);
    }
}

extern "C" void kernel_launch(void* const* d_in, const int* in_sizes, int n_in,
                              void* d_out, int out_size)
{
    const float* boxes = (const float*)d_in[0];
    const float* f0    = (const float*)d_in[1];
    const float* f1    = (const float*)d_in[2];
    const float* f2    = (const float*)d_in[3];
    const float* f3    = (const float*)d_in[4];
    const float* f4    = (const float*)d_in[5];
    const int*   ishp  = (const int*)d_in[6];

    const int BN = in_sizes[0] / 4;                    // B*N boxes
    const int B  = in_sizes[1] / (256 * 256 * 256);    // feat0 = B*256*256*256
    const int N  = BN / B;

    // 3 blocks per SM (444 on 148-SM GB300), each with 4-5 contiguous boxes
    int grid = 444;
    if ((BN + 6) / 7 > grid) grid = (BN + 6) / 7;      // cap boxes/block at 7
    const int chunk = BN / grid;
    const int rem   = BN % grid;

    roialign_kernel<<<grid, 256>>>(boxes, f0, f1, f2, f3, f4, ishp,
                                   (float*)d_out, N, chunk, rem);
}

// round 16
// speedup vs baseline: 1.0270x; 1.0270x over previous
#include <cuda_runtime.h>
#include <cstdint>

// RoiAlign FPN: B=2, N=1000, CROP=7x7, C=256, levels 256/128/64/32/16 (NHWC f32).
// 296 blocks x 320 threads; each block owns <=7 contiguous boxes.
// Phase 1: per-pixel params into smem (corner-00 absolute byte address +
// dx/dy byte deltas in one uint4).
// Phase 2: depth-3 zero-rotation pipeline. CHANNEL REMAP: thread c owns float
// pairs {2c,2c+1} and {128+2c,128+2c+1}, so every corner read is 2x contiguous
// LDG.64 (one warp = 256B = 2 sectors -> 1 replay instead of 3 per LDG.128),
// cutting L1tex within-LDG replay wavefronts ~15% per pixel.

#define COMPUTE_AND_REFILL(L00,H00,L01,H01,L10,H10,L11,H11, QB, Q, NEXTQ)     \
    do {                                                                      \
        const int q_ = (Q);                                                   \
        const float lx_ = QB.x, ly_ = QB.y, okf_ = QB.z;                      \
        float2 vLo_, vHi_;                                                    \
        float t_, btm_;                                                       \
        t_ = L00.x + lx_ * (L01.x - L00.x);                                   \
        btm_ = L10.x + lx_ * (L11.x - L10.x);                                 \
        vLo_.x = (t_ + ly_ * (btm_ - t_)) * okf_;                             \
        t_ = L00.y + lx_ * (L01.y - L00.y);                                   \
        btm_ = L10.y + lx_ * (L11.y - L10.y);                                 \
        vLo_.y = (t_ + ly_ * (btm_ - t_)) * okf_;                             \
        t_ = H00.x + lx_ * (H01.x - H00.x);                                   \
        btm_ = H10.x + lx_ * (H11.x - H10.x);                                 \
        vHi_.x = (t_ + ly_ * (btm_ - t_)) * okf_;                             \
        t_ = H00.y + lx_ * (H01.y - H00.y);                                   \
        btm_ = H10.y + lx_ * (H11.y - H10.y);                                 \
        vHi_.y = (t_ + ly_ * (btm_ - t_)) * okf_;                             \
        if (q_ < total) {                                                     \
            char* od_ = outB + (long)q_ * 1024;                               \
            *(float2*)(od_)       = vLo_;                                     \
            *(float2*)(od_ + 512) = vHi_;                                     \
        }                                                                     \
        /* tail-safe refill index: always a written entry */                  \
        const int nq_ = ((NEXTQ) < total) ? (NEXTQ)                           \
                        : ((q_ < total) ? q_ : 0);                            \
        const uint4 qa_ = s_a[nq_];                                           \
        QB = s_b[nq_];                                                        \
        const char* base_ = (const char*)                                     \
            (((uint64_t)qa_.y << 32) | qa_.x) + coff;                         \
        L00 = __ldg((const float2*)(base_));                                  \
        H00 = __ldg((const float2*)(base_ + 512));                            \
        L01 = __ldg((const float2*)(base_ + qa_.z));                          \
        H01 = __ldg((const float2*)(base_ + qa_.z + 512));                    \
        L10 = __ldg((const float2*)(base_ + qa_.w));                          \
        H10 = __ldg((const float2*)(base_ + qa_.w + 512));                    \
        L11 = __ldg((const float2*)(base_ + qa_.z + qa_.w));                  \
        H11 = __ldg((const float2*)(base_ + qa_.z + qa_.w + 512));            \
    } while (0)

#define PROLOGUE_FILL(L00,H00,L01,H01,L10,H10,L11,H11, QB, P)                 \
    do {                                                                      \
        const uint4 qa_ = s_a[(P)];                                           \
        QB = s_b[(P)];                                                        \
        const char* base_ = (const char*)                                     \
            (((uint64_t)qa_.y << 32) | qa_.x) + coff;                         \
        L00 = __ldg((const float2*)(base_));                                  \
        H00 = __ldg((const float2*)(base_ + 512));                            \
        L01 = __ldg((const float2*)(base_ + qa_.z));                          \
        H01 = __ldg((const float2*)(base_ + qa_.z + 512));                    \
        L10 = __ldg((const float2*)(base_ + qa_.w));                          \
        H10 = __ldg((const float2*)(base_ + qa_.w + 512));                    \
        L11 = __ldg((const float2*)(base_ + qa_.z + qa_.w));                  \
        H11 = __ldg((const float2*)(base_ + qa_.z + qa_.w + 512));            \
    } while (0)

__global__ __launch_bounds__(320, 2) void roialign_kernel(
    const float* __restrict__ boxes,
    const float* __restrict__ f0, const float* __restrict__ f1,
    const float* __restrict__ f2, const float* __restrict__ f3,
    const float* __restrict__ f4,
    const int*   __restrict__ image_shape,
    float*       __restrict__ out,
    int N, int chunk, int rem)
{
    __shared__ uint4  s_a[343];     // addr00_lo, addr00_hi, dx_bytes, dy_bytes
    __shared__ float4 s_b[343];     // lx, ly, okf, 0

    const int bid = blockIdx.x;
    const int tid = threadIdx.x;

    const int start = bid * chunk + min(bid, rem);
    const int nb    = chunk + (bid < rem ? 1 : 0);   // <= 7
    const int total = nb * 49;                       // >= 294 for BN=2000

    // ---------------- Phase 1: params for all nb*49 pixels -------------------
    for (int q = tid; q < total; q += 320) {
        const int bl   = q / 49;
        const int pixl = q % 49;
        const int boxg = start + bl;

        // NOTE: reference unpacks boxes[:,0] as "y1" though setup stacked
        // [x1,y1,x2,y2]; features are square so it's a consistent transpose.
        const float a0 = __ldg(boxes + (size_t)boxg * 4 + 0);
        const float a1 = __ldg(boxes + (size_t)boxg * 4 + 1);
        const float a2 = __ldg(boxes + (size_t)boxg * 4 + 2);
        const float a3 = __ldg(boxes + (size_t)boxg * 4 + 3);

        // lvl = clip(round(log2(sqrt(h*w) / (56/sqrt(area)))), 0, 4)
        const float h     = a3 - a1;
        const float w     = a2 - a0;
        const float area  = (float)(image_shape[0] * image_shape[1]);
        const float denom = 56.0f / sqrtf(area);
        int lvl = (int)rintf(log2f(sqrtf(h * w) / denom));  // round-half-even
        lvl = min(max(lvl, 0), 4);

        const int S = 256 >> lvl;
        const float* feat = (lvl == 0) ? f0 : (lvl == 1) ? f1
                          : (lvl == 2) ? f2 : (lvl == 3) ? f3 : f4;

        const float Hf = (float)(S - 1);
        const int gy = pixl / 7;
        const int gx = pixl % 7;

        // Exact reference op order: ys = y1*Hf + gy*((y2-y1)*Hf/6)
        const float ys = a0 * Hf + (float)gy * (((a2 - a0) * Hf) / 6.0f);
        const float xs = a1 * Hf + (float)gx * (((a3 - a1) * Hf) / 6.0f);

        const float y0f = floorf(ys);
        const float x0f = floorf(xs);
        const float ly  = ys - y0f;
        const float lx  = xs - x0f;

        const int y0 = (int)fminf(fmaxf(y0f,        0.0f), Hf);
        const int y1 = (int)fminf(fmaxf(y0f + 1.0f, 0.0f), Hf);
        const int x0 = (int)fminf(fmaxf(x0f,        0.0f), Hf);
        const int x1 = (int)fminf(fmaxf(x0f + 1.0f, 0.0f), Hf);

        const float okf = ((ys >= 0.0f) & (ys <= Hf) &
                           (xs >= 0.0f) & (xs <= Hf)) ? 1.0f : 0.0f;

        const int bS = (boxg / N) * S;
        // absolute byte address of corner (y0,x0); row stride = S*1024 bytes,
        // col stride = 1024 bytes (C=256 floats)
        const uint64_t addr00 = (uint64_t)feat
                              + ((uint64_t)(bS + y0) * S + x0) * 1024u;
        const uint32_t dx = (uint32_t)(x1 - x0) * 1024u;          // 0 or 1024
        const uint32_t dy = (uint32_t)(y1 - y0) * (uint32_t)S * 1024u;

        s_a[q] = make_uint4((uint32_t)addr00, (uint32_t)(addr00 >> 32), dx, dy);
        s_b[q] = make_float4(lx, ly, okf, 0.0f);
    }
    __syncthreads();

    // ---------------- Phase 2: depth-3, zero-rotation pipeline ---------------
    const int psub = tid >> 6;            // pixel slot 0..4
    const int c    = tid & 63;            // channel-pair lane 0..63
    const uint32_t coff = (uint32_t)c * 8u;   // byte offset of this lane's pair
    char* outB = (char*)out + (long)start * 49 * 1024 + coff;

    // Prologue: fill S0 (p), S1 (p+5), S2 (p+10); total>=294 so all valid.
    const int p0 = psub;
    float2 AL00, AH00, AL01, AH01, AL10, AH10, AL11, AH11; float4 qbA;
    float2 BL00, BH00, BL01, BH01, BL10, BH10, BL11, BH11; float4 qbB;
    float2 CL00, CH00, CL01, CH01, CL10, CH10, CL11, CH11; float4 qbC;
    PROLOGUE_FILL(AL00,AH00,AL01,AH01,AL10,AH10,AL11,AH11, qbA, p0);
    PROLOGUE_FILL(BL00,BH00,BL01,BH01,BL10,BH10,BL11,BH11, qbB, p0 + 5);
    PROLOGUE_FILL(CL00,CH00,CL01,CH01,CL10,CH10,CL11,CH11, qbC, p0 + 10);

    #pragma unroll 1
    for (int p = p0; p < total; p += 15) {
        // body 0: pixel p, refill S0 with p+15 (used 3 bodies later)
        COMPUTE_AND_REFILL(AL00,AH00,AL01,AH01,AL10,AH10,AL11,AH11, qbA,
                           p,      p + 15);
        // body 1: pixel p+5, refill S1 with p+20
        COMPUTE_AND_REFILL(BL00,BH00,BL01,BH01,BL10,BH10,BL11,BH11, qbB,
                           p + 5,  p + 20);
        // body 2: pixel p+10, refill S2 with p+25
        COMPUTE_AND_REFILL(CL00,CH00,CL01,CH01,CL10,CH10,CL11,CH11, qbC,
                           p + 10, p + 25);
    }
}

extern "C" void kernel_launch(void* const* d_in, const int* in_sizes, int n_in,
                              void* d_out, int out_size)
{
    const float* boxes = (const float*)d_in[0];
    const float* f0    = (const float*)d_in[1];
    const float* f1    = (const float*)d_in[2];
    const float* f2    = (const float*)d_in[3];
    const float* f3    = (const float*)d_in[4];
    const float* f4    = (const float*)d_in[5];
    const int*   ishp  = (const int*)d_in[6];

    const int BN = in_sizes[0] / 4;                    // B*N boxes
    const int B  = in_sizes[1] / (256 * 256 * 256);    // feat0 = B*256*256*256
    const int N  = BN / B;

    int grid = 296;
    if ((BN + 6) / 7 > grid) grid = (BN + 6) / 7;      // cap boxes/block at 7
    const int chunk = BN / grid;
    const int rem   = BN % grid;

    roialign_kernel<<<grid, 320>>>(boxes, f0, f1, f2, f3, f4, ishp,
                                   (float*)d_out, N, chunk, rem);
}

// round 17
// speedup vs baseline: 1.0982x; 1.0693x over previous
#include <cuda_runtime.h>

// RoiAlign FPN: B=2, N=1000, CROP=7x7, C=256, levels 256/128/64/32/16 (NHWC f32).
// CHAMPION (R13): 296 blocks x 320 threads; each block owns <=7 contiguous
// boxes. Phase 1: params + per-pixel feat pointer into smem. Phase 2: flat
// pixel loop, 5 slots x 64 float4 channel groups, DEPTH-3 software pipeline
// via manual 3-body unroll with static register sets (S0/S1/S2), zero rotation
// MOVs; tail refills clamp to index 0 (always initialized).
// Measured: 33.28us total / 32.67us hot, regs=94, rel_err 5e-6.

#define C4 64  // 256 channels / 4

#define COMPUTE_AND_REFILL(S00, S01, S10, S11, QB, Q, NEXTQ)                  \
    do {                                                                      \
        const int q_ = (Q);                                                   \
        const float lx_ = QB.x, ly_ = QB.y, okf_ = QB.z;                      \
        float4 val_;                                                          \
        float t_, btm_;                                                       \
        t_ = S00.x + lx_ * (S01.x - S00.x);                                   \
        btm_ = S10.x + lx_ * (S11.x - S10.x);                                 \
        val_.x = (t_ + ly_ * (btm_ - t_)) * okf_;                             \
        t_ = S00.y + lx_ * (S01.y - S00.y);                                   \
        btm_ = S10.y + lx_ * (S11.y - S10.y);                                 \
        val_.y = (t_ + ly_ * (btm_ - t_)) * okf_;                             \
        t_ = S00.z + lx_ * (S01.z - S00.z);                                   \
        btm_ = S10.z + lx_ * (S11.z - S10.z);                                 \
        val_.z = (t_ + ly_ * (btm_ - t_)) * okf_;                             \
        t_ = S00.w + lx_ * (S01.w - S00.w);                                   \
        btm_ = S10.w + lx_ * (S11.w - S10.w);                                 \
        val_.w = (t_ + ly_ * (btm_ - t_)) * okf_;                             \
        if (q_ < total) out4[(long)q_ * C4] = val_;                           \
        /* tail-safe refill index: always a written s_fpp/s_a/s_b entry */    \
        const int nq_ = ((NEXTQ) < total) ? (NEXTQ)                           \
                        : ((q_ < total) ? q_ : 0);                            \
        const float4* nfp_ = s_fpp[nq_];                                      \
        const float4 nqa_ = s_a[nq_];                                         \
        QB = s_b[nq_];                                                        \
        S00 = __ldg(nfp_ + __float_as_int(nqa_.x) + c);                       \
        S01 = __ldg(nfp_ + __float_as_int(nqa_.y) + c);                       \
        S10 = __ldg(nfp_ + __float_as_int(nqa_.z) + c);                       \
        S11 = __ldg(nfp_ + __float_as_int(nqa_.w) + c);                       \
    } while (0)

__global__ __launch_bounds__(320, 2) void roialign_kernel(
    const float* __restrict__ boxes,
    const float* __restrict__ f0, const float* __restrict__ f1,
    const float* __restrict__ f2, const float* __restrict__ f3,
    const float* __restrict__ f4,
    const int*   __restrict__ image_shape,
    float*       __restrict__ out,
    int N, int chunk, int rem)
{
    __shared__ float4 s_a[343];                // corner indices (int bitcast)
    __shared__ float4 s_b[343];                // lx, ly, okf, 0
    __shared__ const float4* s_fpp[343];       // per-pixel level base pointer

    const int bid = blockIdx.x;
    const int tid = threadIdx.x;

    const int start = bid * chunk + min(bid, rem);
    const int nb    = chunk + (bid < rem ? 1 : 0);   // <= 7
    const int total = nb * 49;                       // >= 294 for BN=2000

    // ---------------- Phase 1: params for all nb*49 pixels -------------------
    for (int q = tid; q < total; q += 320) {
        const int bl   = q / 49;
        const int pixl = q % 49;
        const int boxg = start + bl;

        // NOTE: reference unpacks boxes[:,0] as "y1" though setup stacked
        // [x1,y1,x2,y2]; features are square so it's a consistent transpose.
        const float a0 = __ldg(boxes + (size_t)boxg * 4 + 0);
        const float a1 = __ldg(boxes + (size_t)boxg * 4 + 1);
        const float a2 = __ldg(boxes + (size_t)boxg * 4 + 2);
        const float a3 = __ldg(boxes + (size_t)boxg * 4 + 3);

        // lvl = clip(round(log2(sqrt(h*w) / (56/sqrt(area)))), 0, 4)
        const float h     = a3 - a1;
        const float w     = a2 - a0;
        const float area  = (float)(image_shape[0] * image_shape[1]);
        const float denom = 56.0f / sqrtf(area);
        int lvl = (int)rintf(log2f(sqrtf(h * w) / denom));  // round-half-even
        lvl = min(max(lvl, 0), 4);

        const int S = 256 >> lvl;
        const float* feat = (lvl == 0) ? f0 : (lvl == 1) ? f1
                          : (lvl == 2) ? f2 : (lvl == 3) ? f3 : f4;
        s_fpp[q] = (const float4*)feat;

        const float Hf = (float)(S - 1);
        const int gy = pixl / 7;
        const int gx = pixl % 7;

        // Exact reference op order: ys = y1*Hf + gy*((y2-y1)*Hf/6)
        const float ys = a0 * Hf + (float)gy * (((a2 - a0) * Hf) / 6.0f);
        const float xs = a1 * Hf + (float)gx * (((a3 - a1) * Hf) / 6.0f);

        const float y0f = floorf(ys);
        const float x0f = floorf(xs);
        const float ly  = ys - y0f;
        const float lx  = xs - x0f;

        const int y0 = (int)fminf(fmaxf(y0f,        0.0f), Hf);
        const int y1 = (int)fminf(fmaxf(y0f + 1.0f, 0.0f), Hf);
        const int x0 = (int)fminf(fmaxf(x0f,        0.0f), Hf);
        const int x1 = (int)fminf(fmaxf(x0f + 1.0f, 0.0f), Hf);

        const float okf = ((ys >= 0.0f) & (ys <= Hf) &
                           (xs >= 0.0f) & (xs <= Hf)) ? 1.0f : 0.0f;

        const int bS = (boxg / N) * S;
        const int r0 = (bS + y0) * S;
        const int r1 = (bS + y1) * S;
        s_a[q] = make_float4(__int_as_float((r0 + x0) * C4),
                             __int_as_float((r0 + x1) * C4),
                             __int_as_float((r1 + x0) * C4),
                             __int_as_float((r1 + x1) * C4));
        s_b[q] = make_float4(lx, ly, okf, 0.0f);
    }
    __syncthreads();

    // ---------------- Phase 2: depth-3, zero-rotation pipeline ---------------
    const int psub = tid >> 6;        // pixel slot 0..4
    const int c    = tid & 63;        // float4 channel group 0..63
    float4* __restrict__ out4 = (float4*)out + (long)start * 49 * C4 + c;

    // Prologue: fill S0 (p), S1 (p+5), S2 (p+10); total>=294 so all valid.
    const int p0 = psub;
    const float4* fpA = s_fpp[p0];
    float4 qbA = s_b[p0];
    float4 qaA = s_a[p0];
    float4 A00 = __ldg(fpA + __float_as_int(qaA.x) + c);
    float4 A01 = __ldg(fpA + __float_as_int(qaA.y) + c);
    float4 A10 = __ldg(fpA + __float_as_int(qaA.z) + c);
    float4 A11 = __ldg(fpA + __float_as_int(qaA.w) + c);

    const float4* fpB = s_fpp[p0 + 5];
    float4 qbB = s_b[p0 + 5];
    float4 qaB = s_a[p0 + 5];
    float4 B00 = __ldg(fpB + __float_as_int(qaB.x) + c);
    float4 B01 = __ldg(fpB + __float_as_int(qaB.y) + c);
    float4 B10 = __ldg(fpB + __float_as_int(qaB.z) + c);
    float4 B11 = __ldg(fpB + __float_as_int(qaB.w) + c);

    const float4* fpC = s_fpp[p0 + 10];
    float4 qbC = s_b[p0 + 10];
    float4 qaC = s_a[p0 + 10];
    float4 C00 = __ldg(fpC + __float_as_int(qaC.x) + c);
    float4 C01 = __ldg(fpC + __float_as_int(qaC.y) + c);
    float4 C10 = __ldg(fpC + __float_as_int(qaC.z) + c);
    float4 C11 = __ldg(fpC + __float_as_int(qaC.w) + c);

    #pragma unroll 1
    for (int p = p0; p < total; p += 15) {
        // body 0: pixel p, refill S0 with p+15 (used 3 bodies later)
        COMPUTE_AND_REFILL(A00, A01, A10, A11, qbA, p,      p + 15);
        // body 1: pixel p+5, refill S1 with p+20
        COMPUTE_AND_REFILL(B00, B01, B10, B11, qbB, p + 5,  p + 20);
        // body 2: pixel p+10, refill S2 with p+25
        COMPUTE_AND_REFILL(C00, C01, C10, C11, qbC, p + 10, p + 25);
    }
}

extern "C" void kernel_launch(void* const* d_in, const int* in_sizes, int n_in,
                              void* d_out, int out_size)
{
    const float* boxes = (const float*)d_in[0];
    const float* f0    = (const float*)d_in[1];
    const float* f1    = (const float*)d_in[2];
    const float* f2    = (const float*)d_in[3];
    const float* f3    = (const float*)d_in[4];
    const float* f4    = (const float*)d_in[5];
    const int*   ishp  = (const int*)d_in[6];

    const int BN = in_sizes[0] / 4;                    // B*N boxes
    const int B  = in_sizes[1] / (256 * 256 * 256);    // feat0 = B*256*256*256
    const int N  = BN / B;

    int grid = 296;
    if ((BN + 6) / 7 > grid) grid = (BN + 6) / 7;      // cap boxes/block at 7
    const int chunk = BN / grid;
    const int rem   = BN % grid;

    roialign_kernel<<<grid, 320>>>(boxes, f0, f1, f2, f3, f4, ishp,
                                   (float*)d_out, N, chunk, rem);
}